// round 3
// baseline (speedup 1.0000x reference)
#include <cuda_runtime.h>

// Inverse 2D DWT, single level. (4,64,256,256) f32 x4 subbands -> (4,64,512,512) f32.
// Warp-autonomous design: one warp owns a full-width (256-col) strip of RW rows.
// Each lane holds 8 adjacent columns as 4 f32x2 registers per subband-row.
//  - Column pass: rolling 3-row register window, each input element loaded once.
//  - Row pass: neighbor columns exchanged with warp shuffles (no smem, no bars).
//  - All arithmetic is packed fp32x2 (FFMA2).

#define HH 256
#define WW 256
#define RW 16          // rows per warp
#define NT 128         // 4 warps per block

typedef unsigned long long u64;

__device__ __forceinline__ u64 pk(float lo, float hi) {
    u64 r; asm("mov.b64 %0, {%1, %2};" : "=l"(r) : "f"(lo), "f"(hi)); return r;
}
__device__ __forceinline__ void unpk(u64 v, float& lo, float& hi) {
    asm("mov.b64 {%0, %1}, %2;" : "=f"(lo), "=f"(hi) : "l"(v));
}
__device__ __forceinline__ float lof(u64 v) { float a, b; unpk(v, a, b); return a; }
__device__ __forceinline__ float hif(u64 v) { float a, b; unpk(v, a, b); return b; }
__device__ __forceinline__ u64 ffma2(u64 a, u64 b, u64 c) {
    u64 d; asm("fma.rn.f32x2 %0, %1, %2, %3;" : "=l"(d) : "l"(a), "l"(b), "l"(c)); return d;
}
__device__ __forceinline__ u64 fmul2(u64 a, u64 b) {
    u64 d; asm("mul.rn.f32x2 %0, %1, %2;" : "=l"(d) : "l"(a), "l"(b)); return d;
}
__device__ __forceinline__ int reflH(int i) {
    return i < 0 ? -i : (i >= HH ? 2 * HH - 2 - i : i);
}
__device__ __forceinline__ float shup(float v) { return __shfl_up_sync(0xffffffffu, v, 1); }
__device__ __forceinline__ float shdn(float v) { return __shfl_down_sync(0xffffffffu, v, 1); }

#define LD4(dst, p, row)                                                     \
    {                                                                        \
        const u64* __q = (const u64*)((p) + (size_t)(row) * WW);             \
        dst[0] = __q[0]; dst[1] = __q[1]; dst[2] = __q[2]; dst[3] = __q[3];  \
    }

__global__ __launch_bounds__(NT)
void idwt2d(const float* __restrict__ ss, const float* __restrict__ sd,
            const float* __restrict__ ds, const float* __restrict__ dd,
            const float* __restrict__ hf, const float* __restrict__ gf,
            float* __restrict__ out)
{
    const int lane = threadIdx.x & 31;
    const int wid  = threadIdx.x >> 5;
    const int bc   = blockIdx.z;
    const int wr0  = blockIdx.y * (4 * RW) + wid * RW;
    const int c    = 8 * lane;

    const size_t inofs = (size_t)bc * (HH * WW) + c;
    const float* __restrict__ pss = ss + inofs;
    const float* __restrict__ psd = sd + inofs;
    const float* __restrict__ pds = ds + inofs;
    const float* __restrict__ pdd = dd + inofs;
    float* __restrict__ pout = out + (size_t)bc * (4 * HH * WW) + 2 * c;

    const float h0 = hf[0], h1 = hf[1], h2 = hf[2], h3 = hf[3], h4 = hf[4], h5 = hf[5];
    const float g0 = gf[0], g1 = gf[1], g2 = gf[2], g3 = gf[3], g4 = gf[4], g5 = gf[5];
    const u64 H0 = pk(h0, h0), H1 = pk(h1, h1), H2 = pk(h2, h2);
    const u64 H3 = pk(h3, h3), H4 = pk(h4, h4), H5 = pk(h5, h5);
    const u64 G0 = pk(g0, g0), G1 = pk(g1, g1), G2 = pk(g2, g2);
    const u64 G3 = pk(g3, g3), G4 = pk(g4, g4), G5 = pk(g5, g5);

    // rolling window: rows r-1 (S0..) and r (S1..)
    u64 S0[4], S1[4], T0[4], T1[4], U0[4], U1[4], V0[4], V1[4];
    const int rm = reflH(wr0 - 1);
    LD4(S0, pss, rm); LD4(T0, psd, rm); LD4(U0, pds, rm); LD4(V0, pdd, rm);
    LD4(S1, pss, wr0); LD4(T1, psd, wr0); LD4(U1, pds, wr0); LD4(V1, pdd, wr0);

    #pragma unroll 2
    for (int i = 0; i < RW; ++i) {
        const int r = wr0 + i;
        const int rn = reflH(r + 1);

        u64 S2[4], T2[4], U2[4], V2[4];
        LD4(S2, pss, rn); LD4(T2, psd, rn); LD4(U2, pds, rn); LD4(V2, pdd, rn);

        // ---- column pass: 4 arrays x 4 u64 ----
        u64 A0[4], A1[4], A2[4], A3[4];
        #pragma unroll
        for (int j = 0; j < 4; ++j) {
            A0[j] = ffma2(H4, S0[j], ffma2(H2, S1[j], ffma2(H0, S2[j],
                    ffma2(G4, T0[j], ffma2(G2, T1[j], fmul2(G0, T2[j]))))));
            A1[j] = ffma2(H5, S0[j], ffma2(H3, S1[j], ffma2(H1, S2[j],
                    ffma2(G5, T0[j], ffma2(G3, T1[j], fmul2(G1, T2[j]))))));
            A2[j] = ffma2(H4, U0[j], ffma2(H2, U1[j], ffma2(H0, U2[j],
                    ffma2(G4, V0[j], ffma2(G2, V1[j], fmul2(G0, V2[j]))))));
            A3[j] = ffma2(H5, U0[j], ffma2(H3, U1[j], ffma2(H1, U2[j],
                    ffma2(G5, V0[j], ffma2(G3, V1[j], fmul2(G1, V2[j]))))));
        }

        // ---- row pass per output row (py=0 uses A0/A2, py=1 uses A1/A3) ----
        #pragma unroll
        for (int py = 0; py < 2; ++py) {
            const u64* X = py ? A1 : A0;   // sv_py
            const u64* Y = py ? A3 : A2;   // dv_py

            // neighbor halo via shuffle; W-reflection at lanes 0/31
            float xm1 = shup(hif(X[3])); if (lane == 0)  xm1 = hif(X[0]);
            float xp8 = shdn(lof(X[0])); if (lane == 31) xp8 = lof(X[3]);
            float ym1 = shup(hif(Y[3])); if (lane == 0)  ym1 = hif(Y[0]);
            float yp8 = shdn(lof(Y[0])); if (lane == 31) yp8 = lof(Y[3]);

            float* __restrict__ prow = pout + (size_t)(2 * r + py) * (2 * WW);

            #pragma unroll
            for (int j = 0; j < 4; ++j) {
                const u64 BX = X[j];
                const u64 AX = pk(j ? hif(X[j - 1]) : xm1, lof(BX));
                const u64 CX = pk(hif(BX), j < 3 ? lof(X[j + 1]) : xp8);
                const u64 BY = Y[j];
                const u64 AY = pk(j ? hif(Y[j - 1]) : ym1, lof(BY));
                const u64 CY = pk(hif(BY), j < 3 ? lof(Y[j + 1]) : yp8);

                const u64 pe = ffma2(H4, AX, ffma2(H2, BX, ffma2(H0, CX,
                               ffma2(G4, AY, ffma2(G2, BY, fmul2(G0, CY))))));
                const u64 po = ffma2(H5, AX, ffma2(H3, BX, ffma2(H1, CX,
                               ffma2(G5, AY, ffma2(G3, BY, fmul2(G1, CY))))));

                float e0, e1, f0, f1;
                unpk(pe, e0, e1); unpk(po, f0, f1);
                *(float4*)(prow + 4 * j) = make_float4(e0, f0, e1, f1);
            }
        }

        // ---- roll the vertical window ----
        #pragma unroll
        for (int j = 0; j < 4; ++j) {
            S0[j] = S1[j]; S1[j] = S2[j];
            T0[j] = T1[j]; T1[j] = T2[j];
            U0[j] = U1[j]; U1[j] = U2[j];
            V0[j] = V1[j]; V1[j] = V2[j];
        }
    }
}

extern "C" void kernel_launch(void* const* d_in, const int* in_sizes, int n_in,
                              void* d_out, int out_size) {
    const float* ss = (const float*)d_in[0];
    const float* sd = (const float*)d_in[1];
    const float* ds = (const float*)d_in[2];
    const float* dd = (const float*)d_in[3];
    const float* h  = (const float*)d_in[4];
    const float* g  = (const float*)d_in[5];
    float* out = (float*)d_out;

    dim3 grid(1, HH / (4 * RW), 4 * 64);   // (1, 4, 256) = 1024 blocks, 4096 warps
    idwt2d<<<grid, NT>>>(ss, sd, ds, dd, h, g, out);
}

// round 4
// speedup vs baseline: 1.1051x; 1.1051x over previous
#include <cuda_runtime.h>

// Inverse 2D DWT, single level. (4,64,256,256) f32 x4 subbands -> (4,64,512,512) f32.
// Warp-autonomous: one warp owns a 64-col strip x RW rows. Each lane owns 2 adjacent
// columns (one f32x2 register per subband-row). Rolling 3-row window, each input
// element loaded once, next row software-pipelined under the row pass.
// Cross-warp halo handled branchlessly: every lane keeps one scalar halo column
// (lanes 0-30: col wb-1 broadcast; lane 31: col wb+64) and runs a scalar column
// pass on it; lane 0 consumes it as v[c-1], lane 31 as v[c+2]. No smem, no bars.

#define HH 256
#define WW 256
#define RW 32
#define NT 128

typedef unsigned long long u64;

__device__ __forceinline__ u64 pk(float lo, float hi) {
    u64 r; asm("mov.b64 %0, {%1, %2};" : "=l"(r) : "f"(lo), "f"(hi)); return r;
}
__device__ __forceinline__ void unpk(u64 v, float& lo, float& hi) {
    asm("mov.b64 {%0, %1}, %2;" : "=f"(lo), "=f"(hi) : "l"(v));
}
__device__ __forceinline__ float lof(u64 v) { float a, b; unpk(v, a, b); return a; }
__device__ __forceinline__ float hif(u64 v) { float a, b; unpk(v, a, b); return b; }
__device__ __forceinline__ u64 ffma2(u64 a, u64 b, u64 c) {
    u64 d; asm("fma.rn.f32x2 %0, %1, %2, %3;" : "=l"(d) : "l"(a), "l"(b), "l"(c)); return d;
}
__device__ __forceinline__ u64 fmul2(u64 a, u64 b) {
    u64 d; asm("mul.rn.f32x2 %0, %1, %2;" : "=l"(d) : "l"(a), "l"(b)); return d;
}
__device__ __forceinline__ int reflH(int i) {
    return i < 0 ? -i : (i >= HH ? 2 * HH - 2 - i : i);
}
__device__ __forceinline__ float shup(float v) { return __shfl_up_sync(0xffffffffu, v, 1); }
__device__ __forceinline__ float shdn(float v) { return __shfl_down_sync(0xffffffffu, v, 1); }
__device__ __forceinline__ u64 ldg2(const float* __restrict__ p, int row) {
    return *(const u64*)(p + (size_t)row * WW);
}

__global__ __launch_bounds__(NT, 5)
void idwt2d(const float* __restrict__ ss, const float* __restrict__ sd,
            const float* __restrict__ ds, const float* __restrict__ dd,
            const float* __restrict__ hf, const float* __restrict__ gf,
            float* __restrict__ out)
{
    const int lane = threadIdx.x & 31;
    const int wid  = threadIdx.x >> 5;     // strip index 0..3
    const int bc   = blockIdx.z;
    const int r0   = blockIdx.y * RW;
    const int wb   = 64 * wid;
    const int c    = wb + 2 * lane;

    // halo column: lanes 0-30 -> reflW(wb-1) (broadcast addr), lane 31 -> reflW(wb+64)
    const int hcol = (lane == 31) ? ((wb + 64 < WW) ? wb + 64 : WW - 2)
                                  : ((wb > 0) ? wb - 1 : 1);

    const size_t base = (size_t)bc * (HH * WW);
    const float* __restrict__ pss = ss + base + c;
    const float* __restrict__ psd = sd + base + c;
    const float* __restrict__ pds = ds + base + c;
    const float* __restrict__ pdd = dd + base + c;
    const float* __restrict__ qss = ss + base + hcol;
    const float* __restrict__ qsd = sd + base + hcol;
    const float* __restrict__ qds = ds + base + hcol;
    const float* __restrict__ qdd = dd + base + hcol;
    float* __restrict__ pout = out + (size_t)bc * (4 * HH * WW) + 2 * c;

    const float h0 = hf[0], h1 = hf[1], h2 = hf[2], h3 = hf[3], h4 = hf[4], h5 = hf[5];
    const float g0 = gf[0], g1 = gf[1], g2 = gf[2], g3 = gf[3], g4 = gf[4], g5 = gf[5];
    const u64 H0 = pk(h0, h0), H1 = pk(h1, h1), H2 = pk(h2, h2);
    const u64 H3 = pk(h3, h3), H4 = pk(h4, h4), H5 = pk(h5, h5);
    const u64 G0 = pk(g0, g0), G1 = pk(g1, g1), G2 = pk(g2, g2);
    const u64 G3 = pk(g3, g3), G4 = pk(g4, g4), G5 = pk(g5, g5);

    // prime 3-row window (rows r0-1, r0, r0+1)
    const int rm = reflH(r0 - 1);
    const int rp = reflH(r0 + 1);
    u64 S0 = ldg2(pss, rm), T0 = ldg2(psd, rm), U0 = ldg2(pds, rm), V0 = ldg2(pdd, rm);
    u64 S1 = ldg2(pss, r0), T1 = ldg2(psd, r0), U1 = ldg2(pds, r0), V1 = ldg2(pdd, r0);
    u64 S2 = ldg2(pss, rp), T2 = ldg2(psd, rp), U2 = ldg2(pds, rp), V2 = ldg2(pdd, rp);
    float hs0 = qss[(size_t)rm * WW], ht0 = qsd[(size_t)rm * WW];
    float hu0 = qds[(size_t)rm * WW], hv0 = qdd[(size_t)rm * WW];
    float hs1 = qss[(size_t)r0 * WW], ht1 = qsd[(size_t)r0 * WW];
    float hu1 = qds[(size_t)r0 * WW], hv1 = qdd[(size_t)r0 * WW];
    float hs2 = qss[(size_t)rp * WW], ht2 = qsd[(size_t)rp * WW];
    float hu2 = qds[(size_t)rp * WW], hv2 = qdd[(size_t)rp * WW];

    #pragma unroll 4
    for (int i = 0; i < RW; ++i) {
        const int r = r0 + i;

        // ---- column pass (f32x2, both owned columns) ----
        const u64 A0 = ffma2(H4, S0, ffma2(H2, S1, ffma2(H0, S2,
                       ffma2(G4, T0, ffma2(G2, T1, fmul2(G0, T2))))));
        const u64 A1 = ffma2(H5, S0, ffma2(H3, S1, ffma2(H1, S2,
                       ffma2(G5, T0, ffma2(G3, T1, fmul2(G1, T2))))));
        const u64 A2 = ffma2(H4, U0, ffma2(H2, U1, ffma2(H0, U2,
                       ffma2(G4, V0, ffma2(G2, V1, fmul2(G0, V2))))));
        const u64 A3 = ffma2(H5, U0, ffma2(H3, U1, ffma2(H1, U2,
                       ffma2(G5, V0, ffma2(G3, V1, fmul2(G1, V2))))));

        // ---- halo column pass (scalar, all lanes uniform) ----
        const float b0 = fmaf(h4, hs0, fmaf(h2, hs1, fmaf(h0, hs2,
                         fmaf(g4, ht0, fmaf(g2, ht1, g0 * ht2)))));
        const float b1 = fmaf(h5, hs0, fmaf(h3, hs1, fmaf(h1, hs2,
                         fmaf(g5, ht0, fmaf(g3, ht1, g1 * ht2)))));
        const float b2 = fmaf(h4, hu0, fmaf(h2, hu1, fmaf(h0, hu2,
                         fmaf(g4, hv0, fmaf(g2, hv1, g0 * hv2)))));
        const float b3 = fmaf(h5, hu0, fmaf(h3, hu1, fmaf(h1, hu2,
                         fmaf(g5, hv0, fmaf(g3, hv1, g1 * hv2)))));

        // ---- roll window + issue next row's loads early (hidden under row pass) ----
        S0 = S1; S1 = S2; T0 = T1; T1 = T2;
        U0 = U1; U1 = U2; V0 = V1; V1 = V2;
        hs0 = hs1; hs1 = hs2; ht0 = ht1; ht1 = ht2;
        hu0 = hu1; hu1 = hu2; hv0 = hv1; hv1 = hv2;
        const int rn = reflH(r + 2);
        S2 = ldg2(pss, rn); T2 = ldg2(psd, rn);
        U2 = ldg2(pds, rn); V2 = ldg2(pdd, rn);
        hs2 = qss[(size_t)rn * WW]; ht2 = qsd[(size_t)rn * WW];
        hu2 = qds[(size_t)rn * WW]; hv2 = qdd[(size_t)rn * WW];

        // ---- row pass: py=0 uses (A0,A2,b0,b2); py=1 uses (A1,A3,b1,b3) ----
        #pragma unroll
        for (int py = 0; py < 2; ++py) {
            const u64 X = py ? A1 : A0;
            const u64 Y = py ? A3 : A2;
            const float hx = py ? b1 : b0;
            const float hy = py ? b3 : b2;

            float xm = shup(hif(X)); if (lane == 0)  xm = hx;   // v[c-1]
            float xp = shdn(lof(X)); if (lane == 31) xp = hx;   // v[c+2]
            float ym = shup(hif(Y)); if (lane == 0)  ym = hy;
            float yp = shdn(lof(Y)); if (lane == 31) yp = hy;

            const u64 AX = pk(xm, lof(X)), CX = pk(hif(X), xp);
            const u64 AY = pk(ym, lof(Y)), CY = pk(hif(Y), yp);

            const u64 pe = ffma2(H4, AX, ffma2(H2, X, ffma2(H0, CX,
                           ffma2(G4, AY, ffma2(G2, Y, fmul2(G0, CY))))));
            const u64 po = ffma2(H5, AX, ffma2(H3, X, ffma2(H1, CX,
                           ffma2(G5, AY, ffma2(G3, Y, fmul2(G1, CY))))));

            float e0, e1, f0, f1;
            unpk(pe, e0, e1); unpk(po, f0, f1);
            *(float4*)(pout + (size_t)(2 * r + py) * (2 * WW)) = make_float4(e0, f0, e1, f1);
        }
    }
}

extern "C" void kernel_launch(void* const* d_in, const int* in_sizes, int n_in,
                              void* d_out, int out_size) {
    const float* ss = (const float*)d_in[0];
    const float* sd = (const float*)d_in[1];
    const float* ds = (const float*)d_in[2];
    const float* dd = (const float*)d_in[3];
    const float* h  = (const float*)d_in[4];
    const float* g  = (const float*)d_in[5];
    float* out = (float*)d_out;

    dim3 grid(1, HH / RW, 4 * 64);   // (1, 8, 256) = 2048 blocks x 4 warps
    idwt2d<<<grid, NT>>>(ss, sd, ds, dd, h, g, out);
}